// round 14
// baseline (speedup 1.0000x reference)
#include <cuda_runtime.h>
#include <cstdint>

// 3-stage ring as R13, but tiles are fetched with cp.async.bulk (UBLKCP):
// thread 0 issues 2 bulk copies (12KB each) per iteration, completion via
// smem mbarrier (expect_tx = 24KB). No per-thread LDGSTS, no per-thread
// address math — the bulk engine owns the copy; warps only compute.
// 72KB dynamic smem -> 3 CTAs/SM, GRID = 152*3 = 456 = one wave.

#define GRID       456
#define BLOCK      256
#define TILE_F     3072             // floats per array per tile
#define TILE_BYTES 12288            // bytes  per array per tile
#define STAGES     3
#define SMEM_DYN   (STAGES * 2 * TILE_BYTES)   // 73728 B

__device__ float        g_partials[GRID];
__device__ unsigned int g_ticket = 0;

extern __shared__ char sbuf[];      // [stage][arr][TILE_BYTES]

__device__ __forceinline__ char* stg(int s, int arr) {
    return sbuf + (s * 2 + arr) * TILE_BYTES;
}

__device__ __forceinline__ uint32_t s2u(const void* p) {
    uint32_t a;
    asm("{ .reg .u64 t; cvta.to.shared.u64 t, %1; cvt.u32.u64 %0, t; }"
        : "=r"(a) : "l"(p));
    return a;
}

#define MBAR_INIT(addr, cnt) \
    asm volatile("mbarrier.init.shared.b64 [%0], %1;" \
                 :: "r"(addr), "r"(cnt) : "memory")

#define MBAR_EXPECT_TX(addr, bytes) \
    asm volatile("mbarrier.arrive.expect_tx.shared.b64 _, [%0], %1;" \
                 :: "r"(addr), "r"(bytes) : "memory")

#define BULK_G2S(dst_smem, src_gmem, bytes, bar_smem) \
    asm volatile("cp.async.bulk.shared::cta.global.mbarrier::complete_tx::bytes " \
                 "[%0], [%1], %2, [%3];" \
                 :: "r"(dst_smem), "l"(src_gmem), "r"(bytes), "r"(bar_smem) : "memory")

#define MBAR_WAIT(addr, parity) do {                                          \
    uint32_t _m = (addr); uint32_t _p = (parity); uint32_t _done;             \
    asm volatile("{\n\t.reg .pred p;\n\t"                                     \
        "mbarrier.try_wait.parity.acquire.cta.shared::cta.b64 p, [%1], %2;\n\t" \
        "selp.b32 %0, 1, 0, p;\n\t}"                                          \
        : "=r"(_done) : "r"(_m), "r"(_p) : "memory");                         \
    if (!_done) {                                                             \
        asm volatile("{\n\t.reg .pred P1;\n\t"                                \
            "WL_%=:\n\t"                                                      \
            "mbarrier.try_wait.parity.acquire.cta.shared::cta.b64 P1, [%0], %1, 0x989680;\n\t" \
            "@P1 bra.uni WD_%=;\n\t"                                          \
            "bra.uni WL_%=;\n\t"                                              \
            "WD_%=:\n\t}"                                                     \
            :: "r"(_m), "r"(_p) : "memory");                                  \
    }                                                                         \
} while (0)

__global__ void __launch_bounds__(BLOCK)
dist_mean_kernel(const char* __restrict__ pbase, const char* __restrict__ tbase,
                 int ntiles, int n_elem, double inv_count,
                 float* __restrict__ out)
{
    __shared__ alignas(8) unsigned long long mbar[STAGES];
    const int tid = threadIdx.x;
    const uint32_t mb0 = s2u(&mbar[0]);
    float acc = 0.0f;

    if (tid == 0) {
        #pragma unroll
        for (int s = 0; s < STAGES; s++) MBAR_INIT(mb0 + s * 8, 1);
    }
    __syncthreads();

    // ---- remainder triplets beyond ntiles*TILE_F (zero for this shape) ----
    {
        const int rem_trip = (n_elem - ntiles * TILE_F) / 3;
        if (blockIdx.x == 0 && rem_trip > 0) {
            const float* pf = (const float*)pbase + ntiles * TILE_F;
            const float* tf = (const float*)tbase + ntiles * TILE_F;
            for (int i = tid; i < rem_trip; i += BLOCK) {
                float a = pf[3*i+0] - tf[3*i+0];
                float b = pf[3*i+1] - tf[3*i+1];
                float c = pf[3*i+2] - tf[3*i+2];
                acc += sqrtf(fmaf(a, a, fmaf(b, b, c * c)));
            }
        }
    }

    // ---- prologue: bulk-fetch tiles t0,t1 into stages 0,1 ----
    if (tid == 0) {
        #pragma unroll
        for (int k = 0; k < STAGES - 1; k++) {
            const int tile = blockIdx.x + k * GRID;
            if (tile < ntiles) {
                MBAR_EXPECT_TX(mb0 + k * 8, 2 * TILE_BYTES);
                BULK_G2S(s2u(stg(k, 0)), pbase + (size_t)tile * TILE_BYTES,
                         TILE_BYTES, mb0 + k * 8);
                BULK_G2S(s2u(stg(k, 1)), tbase + (size_t)tile * TILE_BYTES,
                         TILE_BYTES, mb0 + k * 8);
            }
        }
    }

    // ---- main loop: wait tile t, ONE barrier, prefetch t+2, compute ----
    int s = 0, ph = 0;
    for (int t = blockIdx.x; t < ntiles; t += GRID) {
        MBAR_WAIT(mb0 + s * 8, ph);            // tile t landed in stage s
        __syncthreads();                        // iter t-1 compute done everywhere
                                                // -> safe to overwrite stage s+2 (== s-1)
        if (tid == 0) {
            const int pf = t + 2 * GRID;
            if (pf < ntiles) {
                int sp = s + 2; if (sp >= STAGES) sp -= STAGES;
                MBAR_EXPECT_TX(mb0 + sp * 8, 2 * TILE_BYTES);
                BULK_G2S(s2u(stg(sp, 0)), pbase + (size_t)pf * TILE_BYTES,
                         TILE_BYTES, mb0 + sp * 8);
                BULK_G2S(s2u(stg(sp, 1)), tbase + (size_t)pf * TILE_BYTES,
                         TILE_BYTES, mb0 + sp * 8);
            }
        }

        // compute: 12 consecutive floats = 4 triplets per thread (conflict-free)
        const float4* ps = (const float4*)(stg(s, 0) + tid * 48);
        const float4* ts = (const float4*)(stg(s, 1) + tid * 48);
        float4 p0 = ps[0], p1 = ps[1], p2 = ps[2];
        float4 t0 = ts[0], t1 = ts[1], t2 = ts[2];

        float a, b, c;
        a = p0.x - t0.x; b = p0.y - t0.y; c = p0.z - t0.z;
        acc += sqrtf(fmaf(a, a, fmaf(b, b, c * c)));
        a = p0.w - t0.w; b = p1.x - t1.x; c = p1.y - t1.y;
        acc += sqrtf(fmaf(a, a, fmaf(b, b, c * c)));
        a = p1.z - t1.z; b = p1.w - t1.w; c = p2.x - t2.x;
        acc += sqrtf(fmaf(a, a, fmaf(b, b, c * c)));
        a = p2.y - t2.y; b = p2.z - t2.z; c = p2.w - t2.w;
        acc += sqrtf(fmaf(a, a, fmaf(b, b, c * c)));

        if (++s == STAGES) { s = 0; ph ^= 1; }
    }

    // ---- all issued copies were consumed; reuse smem as reduction scratch ----
    __syncthreads();

    float*  sm_f  = (float*)(sbuf + 0);
    int*    sm_fl = (int*)(sbuf + 64);
    double* sm_d  = (double*)(sbuf + 128);

    #pragma unroll
    for (int o = 16; o > 0; o >>= 1)
        acc += __shfl_down_sync(0xffffffffu, acc, o);
    if ((tid & 31) == 0) sm_f[tid >> 5] = acc;
    __syncthreads();

    if (tid < 32) {
        float v = (tid < BLOCK / 32) ? sm_f[tid] : 0.0f;
        #pragma unroll
        for (int o = 4; o > 0; o >>= 1)
            v += __shfl_down_sync(0xffffffffu, v, o);
        if (tid == 0) {
            g_partials[blockIdx.x] = v;
            __threadfence();
            unsigned int tk = atomicInc(&g_ticket, GRID - 1);
            sm_fl[0] = (tk == GRID - 1) ? 1 : 0;
        }
    }
    __syncthreads();
    if (!sm_fl[0]) return;

    // ---- last block: deterministic final reduce ----
    double dacc = 0.0;
    #pragma unroll
    for (int i = tid; i < GRID; i += BLOCK)
        dacc += (double)g_partials[i];

    #pragma unroll
    for (int o = 16; o > 0; o >>= 1)
        dacc += __shfl_down_sync(0xffffffffu, dacc, o);
    if ((tid & 31) == 0) sm_d[tid >> 5] = dacc;
    __syncthreads();

    if (tid == 0) {
        double v = 0.0;
        #pragma unroll
        for (int i = 0; i < BLOCK / 32; i++) v += sm_d[i];
        out[0] = (float)(v * inv_count);
    }
}

extern "C" void kernel_launch(void* const* d_in, const int* in_sizes, int n_in,
                              void* d_out, int out_size)
{
    const char* pred = (const char*)d_in[0];
    const char* targ = (const char*)d_in[1];
    float* out = (float*)d_out;

    static int attr_done = 0;
    if (!attr_done) {
        cudaFuncSetAttribute(dist_mean_kernel,
                             cudaFuncAttributeMaxDynamicSharedMemorySize, SMEM_DYN);
        attr_done = 1;
    }

    const int n_elem = in_sizes[0];            // B*63 = 66,060,288 = 3072 * 21504
    const int ntiles = n_elem / TILE_F;
    const long long n_dists = (long long)n_elem / 3;
    const double inv_cnt = 1.0 / (double)n_dists;

    dist_mean_kernel<<<GRID, BLOCK, SMEM_DYN>>>(pred, targ, ntiles, n_elem,
                                                inv_cnt, out);
}